// round 17
// baseline (speedup 1.0000x reference)
#include <cuda_runtime.h>

// Problem constants
#define BB 16
#define NN 4096
#define DD 256
// NS = 8, H = 256, ITERS = 3, SCALE = 1/16

// Output layout (float32, concatenated tuple):
#define O_SLOTS 0
#define O_PR    32768
#define O_PF    65536
#define O_SF    16842752
#define O_ATTNS 33619968

// ---------------- scratch ----------------
__device__ float d_slots[128 * 256];     // current slots
__device__ float d_snew[128 * 256];      // gru output (pre-FFN residual base)
__device__ float d_q[128 * 256];         // q (pre-scaled by SCALE)
__device__ float d_upd[128 * 256];       // un-normalized updates accumulator
__device__ float d_rowsum[128];          // sum_n attn[b,s,n]
__device__ float d_gates[128 * 1536];    // [gi(768) | gh(768)]
__device__ float d_h1[128 * 256];        // relu hidden

// ---------------- helpers ----------------
__device__ __forceinline__ void wreduce8(float a[8]) {
#pragma unroll
    for (int m = 16; m; m >>= 1) {
#pragma unroll
        for (int s = 0; s < 8; ++s)
            a[s] += __shfl_xor_sync(0xffffffffu, a[s], m);
    }
}

__device__ __forceinline__ float pick8(const float a[8], int l) {
    float v = a[0];
    if (l == 1) v = a[1];
    if (l == 2) v = a[2];
    if (l == 3) v = a[3];
    if (l == 4) v = a[4];
    if (l == 5) v = a[5];
    if (l == 6) v = a[6];
    if (l == 7) v = a[7];
    return v;
}

// warp GEMM core: acc[r] = dot(W[j], in_row[r]) for 8 rows; lanes along K.
__device__ __forceinline__ void wdot8(const float4* __restrict__ wrow,
                                      const float4* __restrict__ in4,
                                      int l, float acc[8]) {
    float4 wa = wrow[l], wb = wrow[l + 32];
#pragma unroll
    for (int r = 0; r < 8; ++r) {
        float4 xa = in4[r * 64 + l], xb = in4[r * 64 + 32 + l];
        acc[r] = wa.x * xa.x + wa.y * xa.y + wa.z * xa.z + wa.w * xa.w
               + wb.x * xb.x + wb.y * xb.y + wb.z * xb.z + wb.w * xb.w;
    }
}

// warp-collective LN stats of a 256-row held as 2 float4/lane
__device__ __forceinline__ float2 warp_meanrstd(float4 a, float4 c) {
    float sm = a.x + a.y + a.z + a.w + c.x + c.y + c.z + c.w;
    float sq = a.x * a.x + a.y * a.y + a.z * a.z + a.w * a.w
             + c.x * c.x + c.y * c.y + c.z * c.z + c.w * c.w;
#pragma unroll
    for (int m = 16; m; m >>= 1) {
        sm += __shfl_xor_sync(0xffffffffu, sm, m);
        sq += __shfl_xor_sync(0xffffffffu, sq, m);
    }
    float mean = sm * (1.f / 256.f);
    return make_float2(mean, rsqrtf(sq * (1.f / 256.f) - mean * mean + 1e-5f));
}

__device__ __forceinline__ float4 ln_apply(float4 x, float2 st, float4 g, float4 e) {
    return make_float4((x.x - st.x) * st.y * g.x + e.x,
                       (x.y - st.x) * st.y * g.y + e.y,
                       (x.z - st.x) * st.y * g.z + e.z,
                       (x.w - st.x) * st.y * g.w + e.w);
}

// ---------------- kernels ----------------

// Iteration-0: slots init from mu + LN + q projection + zero upd/rowsum.
// grid = (4 colgroups of 64, 16 batches), 256 threads.
__global__ __launch_bounds__(256) void k_sq0(const float* __restrict__ mu,
                                             const float* __restrict__ Wq,
                                             const float* __restrict__ bq,
                                             const float* __restrict__ gs,
                                             const float* __restrict__ bs) {
    int cg = blockIdx.x, b = blockIdx.y, t = threadIdx.x;
    int w = t >> 5, l = t & 31;
    __shared__ float4 sln4[8 * 64];
    const float4* sr = (const float4*)mu + (size_t)w * 64;  // slot row w
    float4 x0 = sr[l], x1 = sr[l + 32];
    float2 st = warp_meanrstd(x0, x1);
    float4 g0 = ((const float4*)gs)[l], g1 = ((const float4*)gs)[l + 32];
    float4 e0 = ((const float4*)bs)[l], e1 = ((const float4*)bs)[l + 32];
    sln4[w * 64 + l] = ln_apply(x0, st, g0, e0);
    sln4[w * 64 + 32 + l] = ln_apply(x1, st, g1, e1);
    if (cg == 0) {
        ((float4*)d_slots)[(b * 8 + w) * 64 + l] = x0;
        ((float4*)d_slots)[(b * 8 + w) * 64 + 32 + l] = x1;
#pragma unroll
        for (int k = 0; k < 8; ++k) d_upd[(b * 8 + k) * 256 + t] = 0.f;
        if (t < 8) d_rowsum[b * 8 + t] = 0.f;
    }
    __syncthreads();
#pragma unroll
    for (int cw = 0; cw < 8; ++cw) {
        int j = cg * 64 + w * 8 + cw;
        float acc[8];
        wdot8((const float4*)Wq + (size_t)j * 64, sln4, l, acc);
        wreduce8(acc);
        if (l < 8)
            d_q[(b * 8 + l) * 256 + j] = (pick8(acc, l) + bq[j]) * 0.0625f;
    }
}

// Fused attention + updates: per CTA 128 tokens of one batch.
// Phase1 (warp/token): k-LN, dots, softmax->attn smem; v-LN -> vln smem.
// Phase2 (thread/d): acc[s] += attn[s][j] * vln[j][d].
// grid = (32, 16), 256 threads.
__global__ __launch_bounds__(256) void k_av(int it, float* __restrict__ aout_base,
                                            const float* __restrict__ kin,
                                            const float* __restrict__ vin,
                                            const float* __restrict__ gk,
                                            const float* __restrict__ bk,
                                            const float* __restrict__ gv,
                                            const float* __restrict__ bv) {
    int b = blockIdx.y;
    int n0 = blockIdx.x * 128;
    int t = threadIdx.x, w = t >> 5, l = t & 31;
    __shared__ float4 q4[512];          // 8 slots x 64 float4 (8KB)
    __shared__ float4 att4[8 * 32];     // attn [8][128] (4KB)
    __shared__ float4 vln4[32 * 64];    // LN'd v tile [32][256] (32KB)
    float* att = (float*)att4;
    const float4* qg = (const float4*)d_q + b * 512;
    q4[t] = qg[t];
    q4[t + 256] = qg[t + 256];
    __syncthreads();

    const float4* gk4 = (const float4*)gk;
    const float4* bk4 = (const float4*)bk;
    const float4* gv4 = (const float4*)gv;
    const float4* bv4 = (const float4*)bv;

    float acc[8] = {0.f, 0.f, 0.f, 0.f, 0.f, 0.f, 0.f, 0.f};

    for (int c = 0; c < 4; ++c) {
#pragma unroll
        for (int i = 0; i < 4; ++i) {
            int tok = c * 32 + w * 4 + i;
            size_t roff = ((size_t)b * NN + n0 + tok) * DD;
            const float4* kr = (const float4*)(kin + roff);
            const float4* vr = (const float4*)(vin + roff);
            float4 k0 = kr[l], k1 = kr[l + 32];
            float4 v0 = vr[l], v1 = vr[l + 32];
            // k layernorm
            float2 stk = warp_meanrstd(k0, k1);
            k0 = ln_apply(k0, stk, __ldg(gk4 + l), __ldg(bk4 + l));
            k1 = ln_apply(k1, stk, __ldg(gk4 + l + 32), __ldg(bk4 + l + 32));
            // dots vs all 8 slots (q pre-scaled)
            float d8[8];
#pragma unroll
            for (int s = 0; s < 8; ++s) {
                float4 q0 = q4[s * 64 + l];
                float4 q1 = q4[s * 64 + 32 + l];
                d8[s] = k0.x * q0.x + k0.y * q0.y + k0.z * q0.z + k0.w * q0.w
                      + k1.x * q1.x + k1.y * q1.y + k1.z * q1.z + k1.w * q1.w;
            }
            wreduce8(d8);
            float mx = d8[0];
#pragma unroll
            for (int s = 1; s < 8; ++s) mx = fmaxf(mx, d8[s]);
            float e[8], sum = 0.f;
#pragma unroll
            for (int s = 0; s < 8; ++s) { e[s] = __expf(d8[s] - mx); sum += e[s]; }
            float inv = 1.f / sum;
            if (l < 8) att[l * 128 + tok] = pick8(e, l) * inv + 1e-8f;
            // v layernorm -> smem
            float2 stv = warp_meanrstd(v0, v1);
            v0 = ln_apply(v0, stv, __ldg(gv4 + l), __ldg(bv4 + l));
            v1 = ln_apply(v1, stv, __ldg(gv4 + l + 32), __ldg(bv4 + l + 32));
            int tl = tok & 31;
            vln4[tl * 64 + l] = v0;
            vln4[tl * 64 + 32 + l] = v1;
        }
        __syncthreads();
        // phase 2: thread t = dimension d
        {
            const float* vb = (const float*)vln4;
#pragma unroll
            for (int jg = 0; jg < 8; ++jg) {
                float x0 = vb[(jg * 4 + 0) * 256 + t];
                float x1 = vb[(jg * 4 + 1) * 256 + t];
                float x2 = vb[(jg * 4 + 2) * 256 + t];
                float x3 = vb[(jg * 4 + 3) * 256 + t];
#pragma unroll
                for (int s = 0; s < 8; ++s) {
                    float4 av = att4[s * 32 + c * 8 + jg];
                    acc[s] += av.x * x0 + av.y * x1 + av.z * x2 + av.w * x3;
                }
            }
        }
        __syncthreads();
    }
#pragma unroll
    for (int s = 0; s < 8; ++s)
        atomicAdd(&d_upd[(b * 8 + s) * 256 + t], acc[s]);
    // attn global write + rowsum; warp w handles slot row w
    {
        int s = w;
        float4 av = att4[s * 32 + l];
        float* aout = aout_base + ((size_t)(it * BB + b) * 8 + s) * NN + n0;
        ((float4*)aout)[l] = av;
        float rs = av.x + av.y + av.z + av.w;
#pragma unroll
        for (int m = 16; m; m >>= 1) rs += __shfl_xor_sync(0xffffffffu, rs, m);
        if (l == 0) atomicAdd(&d_rowsum[b * 8 + s], rs);
    }
}

// GRU gates. grid = (12 colgroups of 128, 16 rowgroups of 8), 256 threads.
__global__ __launch_bounds__(256) void k_gates(
    const float* __restrict__ Wih, const float* __restrict__ bih,
    const float* __restrict__ Whh, const float* __restrict__ bhh) {
    int cg = blockIdx.x, rg = blockIdx.y, t = threadIdx.x;
    int w = t >> 5, l = t & 31;
    bool useX = cg < 6;
    int row0 = rg * 8;
    __shared__ float in_s[8 * 256];
    __shared__ float irs_sh[8];
    if (t < 8) irs_sh[t] = 1.0f / d_rowsum[row0 + t];
    __syncthreads();
#pragma unroll
    for (int k = 0; k < 8; ++k)
        in_s[k * 256 + t] = useX ? d_upd[(row0 + k) * 256 + t] * irs_sh[k]
                                 : d_slots[(row0 + k) * 256 + t];
    __syncthreads();
    const float* W = useX ? Wih : Whh;
    const float* bias = useX ? bih : bhh;
    const float4* in4 = (const float4*)in_s;
#pragma unroll
    for (int cw = 0; cw < 16; ++cw) {
        int j = cg * 128 + w * 16 + cw;
        int jj = useX ? j : j - 768;
        float acc[8];
        wdot8((const float4*)W + (size_t)jj * 64, in4, l, acc);
        wreduce8(acc);
        if (l < 8)
            d_gates[(size_t)(row0 + l) * 1536 + j] = pick8(acc, l) + bias[jj];
    }
}

// GRU pointwise (recomputed per colgroup, bitwise identical) + LN + W1/relu.
// grid = (8 colgroups of 32, 16 rowgroups of 8), 256 threads.
__global__ __launch_bounds__(256) void k_gruh1(const float* __restrict__ W1,
                                               const float* __restrict__ b1,
                                               const float* __restrict__ gff,
                                               const float* __restrict__ bff) {
    int cg = blockIdx.x, rg = blockIdx.y, t = threadIdx.x;
    int w = t >> 5, l = t & 31;
    int r0 = rg * 8;
    __shared__ float sn_s[8 * 256];
    __shared__ float pre_s[8 * 256];
#pragma unroll
    for (int k = 0; k < 8; ++k) {
        int row = r0 + k;
        const float* g = d_gates + (size_t)row * 1536;
        float ir = g[t], iz = g[t + 256], inn = g[t + 512];
        float hr = g[t + 768], hz = g[t + 1024], hn = g[t + 1280];
        float h = d_slots[row * 256 + t];
        float rr = 1.f / (1.f + __expf(-(ir + hr)));
        float z  = 1.f / (1.f + __expf(-(iz + hz)));
        float ng = tanhf(inn + rr * hn);
        sn_s[k * 256 + t] = (1.f - z) * ng + z * h;
    }
    __syncthreads();
    {   // LN row w (warps 0..7)
        const float4* sn4 = (const float4*)(sn_s + w * 256);
        float4 x0 = sn4[l], x1 = sn4[l + 32];
        float2 st = warp_meanrstd(x0, x1);
        float4 g0 = __ldg((const float4*)gff + l), g1 = __ldg((const float4*)gff + l + 32);
        float4 e0 = __ldg((const float4*)bff + l), e1 = __ldg((const float4*)bff + l + 32);
        ((float4*)(pre_s + w * 256))[l] = ln_apply(x0, st, g0, e0);
        ((float4*)(pre_s + w * 256))[l + 32] = ln_apply(x1, st, g1, e1);
        if (cg == 0) {
            ((float4*)(d_snew + (size_t)(r0 + w) * 256))[l] = x0;
            ((float4*)(d_snew + (size_t)(r0 + w) * 256))[l + 32] = x1;
        }
    }
    __syncthreads();
    const float4* pre4 = (const float4*)pre_s;
#pragma unroll
    for (int cw = 0; cw < 4; ++cw) {
        int j = cg * 32 + w * 4 + cw;
        float acc[8];
        wdot8((const float4*)W1 + (size_t)j * 64, pre4, l, acc);
        wreduce8(acc);
        if (l < 8)
            d_h1[(r0 + l) * 256 + j] = fmaxf(pick8(acc, l) + b1[j], 0.f);
    }
}

// W2-out + residual + slots write + LN + next-iter q + zero upd/rowsum.
// grid = 16 rowgroups of 8, 512 threads (16 warps).
__global__ __launch_bounds__(512) void k_ffoq(const float* __restrict__ W2,
                                              const float* __restrict__ b2,
                                              const float* __restrict__ gs,
                                              const float* __restrict__ bs,
                                              const float* __restrict__ Wq,
                                              const float* __restrict__ bq) {
    int rg = blockIdx.x, t = threadIdx.x;
    int w = t >> 5, l = t & 31;
    int r0 = rg * 8;
    __shared__ float h1s[8 * 256];
    __shared__ float sl_s[8 * 256];
    __shared__ float sln_s[8 * 256];
    for (int idx = t; idx < 2048; idx += 512) h1s[idx] = d_h1[r0 * 256 + idx];
    __syncthreads();
    const float4* h14 = (const float4*)h1s;
#pragma unroll
    for (int cw = 0; cw < 16; ++cw) {
        int j = w * 16 + cw;
        float acc[8];
        wdot8((const float4*)W2 + (size_t)j * 64, h14, l, acc);
        wreduce8(acc);
        if (l < 8)
            sl_s[l * 256 + j] = pick8(acc, l) + b2[j] + d_snew[(r0 + l) * 256 + j];
    }
    __syncthreads();
    for (int idx = t; idx < 2048; idx += 512) {
        d_slots[r0 * 256 + idx] = sl_s[idx];
        d_upd[r0 * 256 + idx] = 0.f;
    }
    if (t < 8) d_rowsum[r0 + t] = 0.f;
    if (w < 8) {  // LN row w
        const float4* s4 = (const float4*)(sl_s + w * 256);
        float4 x0 = s4[l], x1 = s4[l + 32];
        float2 st = warp_meanrstd(x0, x1);
        float4 g0 = __ldg((const float4*)gs + l), g1 = __ldg((const float4*)gs + l + 32);
        float4 e0 = __ldg((const float4*)bs + l), e1 = __ldg((const float4*)bs + l + 32);
        ((float4*)(sln_s + w * 256))[l] = ln_apply(x0, st, g0, e0);
        ((float4*)(sln_s + w * 256))[l + 32] = ln_apply(x1, st, g1, e1);
    }
    __syncthreads();
    const float4* sln4 = (const float4*)sln_s;
#pragma unroll
    for (int cw = 0; cw < 16; ++cw) {
        int j = w * 16 + cw;
        float acc[8];
        wdot8((const float4*)Wq + (size_t)j * 64, sln4, l, acc);
        wreduce8(acc);
        if (l < 8)
            d_q[(r0 + l) * 256 + j] = (pick8(acc, l) + bq[j]) * 0.0625f;
    }
}

// pf/sf + copy slots/pr outputs. grid = (N/128, B), vectorized stores.
__global__ __launch_bounds__(256) void k_final(const float* __restrict__ prompts,
                                               const float* __restrict__ ain_base,
                                               float* __restrict__ out) {
    int b = blockIdx.y;
    int p0 = blockIdx.x * 128;
    int t = threadIdx.x;
    int d4 = t & 63, pg = t >> 6;
    __shared__ float att[8][128];
    const float* ab = ain_base + ((size_t)(2 * BB + b) * 8) * NN + p0;
#pragma unroll
    for (int kk = 0; kk < 4; ++kk) {
        int idx = t + kk * 256;
        int s = idx >> 7, c = idx & 127;
        att[s][c] = ab[(size_t)s * NN + c];
    }
    float4 prv[8], slv[8];
    const float4* pr4 = (const float4*)prompts;
    const float4* sl4 = (const float4*)d_slots;
#pragma unroll
    for (int s = 0; s < 8; ++s) {
        prv[s] = pr4[s * 64 + d4];
        slv[s] = sl4[(b * 8 + s) * 64 + d4];
    }
    __syncthreads();
    float4* pfp = (float4*)(out + O_PF) + ((size_t)b * NN + p0) * 64 + d4;
    float4* sfp = (float4*)(out + O_SF) + ((size_t)b * NN + p0) * 64 + d4;
    for (int i = 0; i < 32; ++i) {
        int p = pg * 32 + i;
        float4 ap = make_float4(0.f, 0.f, 0.f, 0.f);
        float4 as = make_float4(0.f, 0.f, 0.f, 0.f);
#pragma unroll
        for (int s = 0; s < 8; ++s) {
            float a = att[s][p];
            ap.x += prv[s].x * a; ap.y += prv[s].y * a;
            ap.z += prv[s].z * a; ap.w += prv[s].w * a;
            as.x += slv[s].x * a; as.y += slv[s].y * a;
            as.z += slv[s].z * a; as.w += slv[s].w * a;
        }
        pfp[(size_t)p * 64] = ap;
        sfp[(size_t)p * 64] = as;
    }
    if (blockIdx.x == 0 && pg == 0) {
        float4* o1 = (float4*)(out + O_SLOTS);
        float4* o2 = (float4*)(out + O_PR);
#pragma unroll
        for (int s = 0; s < 8; ++s) {
            o1[(b * 8 + s) * 64 + d4] = slv[s];
            o2[(b * 8 + s) * 64 + d4] = prv[s];
        }
    }
}

// ---------------- host ----------------
extern "C" void kernel_launch(void* const* d_in, const int* in_sizes, int n_in,
                              void* d_out, int out_size) {
    (void)in_sizes; (void)n_in; (void)out_size;
    const float* k_inp    = (const float*)d_in[2];
    const float* v_inp    = (const float*)d_in[3];
    const float* slots_mu = (const float*)d_in[4];
    const float* prompts  = (const float*)d_in[5];
    const float* Wq  = (const float*)d_in[6];
    const float* bq  = (const float*)d_in[7];
    const float* Wih = (const float*)d_in[8];
    const float* bih = (const float*)d_in[9];
    const float* Whh = (const float*)d_in[10];
    const float* bhh = (const float*)d_in[11];
    const float* W1  = (const float*)d_in[12];
    const float* b1  = (const float*)d_in[13];
    const float* W2  = (const float*)d_in[14];
    const float* b2  = (const float*)d_in[15];
    const float* gk  = (const float*)d_in[16];
    const float* bk  = (const float*)d_in[17];
    const float* gv  = (const float*)d_in[18];
    const float* bv  = (const float*)d_in[19];
    const float* gs  = (const float*)d_in[20];
    const float* bs  = (const float*)d_in[21];
    const float* gff = (const float*)d_in[22];
    const float* bff = (const float*)d_in[23];

    float* out = (float*)d_out;
    float* attn_out = out + O_ATTNS;

    k_sq0<<<dim3(4, 16), 256>>>(slots_mu, Wq, bq, gs, bs);

    for (int it = 0; it < 3; ++it) {
        k_av<<<dim3(32, 16), 256>>>(it, attn_out, k_inp, v_inp, gk, bk, gv, bv);
        k_gates<<<dim3(12, 16), 256>>>(Wih, bih, Whh, bhh);
        k_gruh1<<<dim3(8, 16), 256>>>(W1, b1, gff, bff);
        k_ffoq<<<16, 512>>>(W2, b2, gs, bs, Wq, bq);
    }

    k_final<<<dim3(NN / 128, BB), 256>>>(prompts, attn_out, out);
}